// round 2
// baseline (speedup 1.0000x reference)
#include <cuda_runtime.h>
#include <math.h>

// Problem constants
#define BV   2
#define NV   2048
#define CV   1024
#define HV   16
#define HDV  64
#define RV   16
#define MROWS (BV*NV)            // 4096
#define LORA_SCALE 2.0f
#define ATTN_SCALE 0.125f        // 64^-0.5

// Scratch (device globals — allocation-free per harness rules)
__device__ float g_q[(size_t)BV*HV*NV*HDV];   // [B,H,N,HD]
__device__ float g_k[(size_t)BV*HV*NV*HDV];
__device__ float g_v[(size_t)BV*HV*NV*HDV];
__device__ float g_o[(size_t)MROWS*CV];       // [B,N,C] attention output

// ---------------------------------------------------------------------------
// QKV GEMM: X[4096,1024] @ W[1024,3072] + bias, scatter into g_q/g_k/g_v
// Tile 64x64, BK=16, 256 threads, 4x4 per thread.
// ---------------------------------------------------------------------------
__global__ __launch_bounds__(256) void qkv_gemm_kernel(
    const float* __restrict__ X, const float* __restrict__ W,
    const float* __restrict__ bias)
{
    __shared__ float As[16][64];
    __shared__ float Bs[16][64];

    const int tid = threadIdx.x;
    const int tx  = tid & 15;
    const int ty  = tid >> 4;
    const int c0  = blockIdx.x * 64;   // output col tile (0..3071)
    const int r0  = blockIdx.y * 64;   // row tile (0..4095)
    const int K   = CV;
    const int Nc  = 3 * CV;

    // loader decomposition
    const int am = tid >> 2;            // 0..63 (A row within tile)
    const int ak = (tid & 3) * 4;       // 0,4,8,12 (A k quad)
    const int bk = tid >> 4;            // 0..15 (B k row)
    const int bc = (tid & 15) * 4;      // B col quad

    float acc[4][4] = {};

    for (int k0 = 0; k0 < K; k0 += 16) {
        float4 a4 = *reinterpret_cast<const float4*>(
            X + (size_t)(r0 + am) * K + k0 + ak);
        As[ak + 0][am] = a4.x;
        As[ak + 1][am] = a4.y;
        As[ak + 2][am] = a4.z;
        As[ak + 3][am] = a4.w;
        *reinterpret_cast<float4*>(&Bs[bk][bc]) =
            *reinterpret_cast<const float4*>(W + (size_t)(k0 + bk) * Nc + c0 + bc);
        __syncthreads();

        #pragma unroll
        for (int kk = 0; kk < 16; ++kk) {
            float4 av = *reinterpret_cast<const float4*>(&As[kk][ty * 4]);
            float4 bv = *reinterpret_cast<const float4*>(&Bs[kk][tx * 4]);
            acc[0][0] += av.x * bv.x; acc[0][1] += av.x * bv.y;
            acc[0][2] += av.x * bv.z; acc[0][3] += av.x * bv.w;
            acc[1][0] += av.y * bv.x; acc[1][1] += av.y * bv.y;
            acc[1][2] += av.y * bv.z; acc[1][3] += av.y * bv.w;
            acc[2][0] += av.z * bv.x; acc[2][1] += av.z * bv.y;
            acc[2][2] += av.z * bv.z; acc[2][3] += av.z * bv.w;
            acc[3][0] += av.w * bv.x; acc[3][1] += av.w * bv.y;
            acc[3][2] += av.w * bv.z; acc[3][3] += av.w * bv.w;
        }
        __syncthreads();
    }

    #pragma unroll
    for (int i = 0; i < 4; ++i) {
        const int row = r0 + ty * 4 + i;
        const int b   = row >> 11;         // /2048
        const int n   = row & 2047;
        #pragma unroll
        for (int j = 0; j < 4; ++j) {
            const int col   = c0 + tx * 4 + j;
            const float val = acc[i][j] + bias[col];
            const int which = col >> 10;         // 0=q,1=k,2=v
            const int rem   = col & 1023;
            const int h     = rem >> 6;
            const int d     = rem & 63;
            float* dst = (which == 0) ? g_q : (which == 1) ? g_k : g_v;
            dst[(((size_t)(b * HV + h) * NV) + n) * HDV + d] = val;
        }
    }
}

// ---------------------------------------------------------------------------
// LoRA: row += 2 * ((row @ A[64,16]) @ Bm[16,64]), one thread per head-row.
// which: 0 -> g_q, 1 -> g_v
// ---------------------------------------------------------------------------
__global__ __launch_bounds__(256) void lora_kernel(
    int which, const float* __restrict__ A, const float* __restrict__ Bm)
{
    __shared__ float sA[HDV * RV];   // 1024
    __shared__ float sB[RV * HDV];   // 1024
    const int tid = threadIdx.x;
    #pragma unroll
    for (int i = 0; i < 4; ++i) {
        sA[tid + i * 256] = A[tid + i * 256];
        sB[tid + i * 256] = Bm[tid + i * 256];
    }
    __syncthreads();

    float* data = which ? g_v : g_q;
    const size_t row = (size_t)blockIdx.x * 256 + tid;   // 0..65535
    float* p = data + row * HDV;

    float xv[64];
    #pragma unroll
    for (int i = 0; i < 16; ++i) {
        float4 t = *reinterpret_cast<const float4*>(p + 4 * i);
        xv[4*i+0] = t.x; xv[4*i+1] = t.y; xv[4*i+2] = t.z; xv[4*i+3] = t.w;
    }

    float r[16] = {};
    #pragma unroll
    for (int d = 0; d < 64; ++d) {
        #pragma unroll
        for (int j = 0; j < 16; ++j)
            r[j] += xv[d] * sA[d * RV + j];
    }

    #pragma unroll
    for (int i = 0; i < 16; ++i) {
        float4 t;
        float o[4];
        #pragma unroll
        for (int q = 0; q < 4; ++q) {
            const int d = 4 * i + q;
            float delta = 0.f;
            #pragma unroll
            for (int j = 0; j < 16; ++j)
                delta += r[j] * sB[j * HDV + d];
            o[q] = xv[d] + LORA_SCALE * delta;
        }
        t.x = o[0]; t.y = o[1]; t.z = o[2]; t.w = o[3];
        *reinterpret_cast<float4*>(p + 4 * i) = t;
    }
}

// ---------------------------------------------------------------------------
// Flash attention (fp32): one thread per query row; K/V tiles (64 keys) in
// smem, scores in 16-key register chunks with online softmax.
// grid: (N/128, B*H), block: 128
// ---------------------------------------------------------------------------
__global__ __launch_bounds__(128) void flash_kernel()
{
    __shared__ float Ks[64 * 64];
    __shared__ float Vs[64 * 64];

    const int tid = threadIdx.x;
    const int bh  = blockIdx.y;                // 0..31
    const int nq  = blockIdx.x * 128 + tid;    // 0..2047

    const float* qp = g_q + ((size_t)bh * NV + nq) * HDV;
    float qr[64];
    #pragma unroll
    for (int i = 0; i < 16; ++i) {
        float4 t = *reinterpret_cast<const float4*>(qp + 4 * i);
        qr[4*i+0] = t.x; qr[4*i+1] = t.y; qr[4*i+2] = t.z; qr[4*i+3] = t.w;
    }

    float m = -INFINITY, l = 0.f;
    float acc[64] = {};

    for (int kt = 0; kt < NV / 64; ++kt) {
        const float4* kp = reinterpret_cast<const float4*>(
            g_k + ((size_t)bh * NV + kt * 64) * HDV);
        const float4* vp = reinterpret_cast<const float4*>(
            g_v + ((size_t)bh * NV + kt * 64) * HDV);
        #pragma unroll
        for (int i = 0; i < 8; ++i) {
            const int idx = tid + i * 128;     // 0..1023 float4
            reinterpret_cast<float4*>(Ks)[idx] = kp[idx];
            reinterpret_cast<float4*>(Vs)[idx] = vp[idx];
        }
        __syncthreads();

        #pragma unroll
        for (int c = 0; c < 4; ++c) {
            float s[16];
            #pragma unroll
            for (int kk = 0; kk < 16; ++kk) {
                const float4* kr = reinterpret_cast<const float4*>(
                    Ks + (c * 16 + kk) * 64);
                float sum = 0.f;
                #pragma unroll
                for (int d4 = 0; d4 < 16; ++d4) {
                    float4 kv = kr[d4];
                    sum += qr[4*d4+0] * kv.x + qr[4*d4+1] * kv.y
                         + qr[4*d4+2] * kv.z + qr[4*d4+3] * kv.w;
                }
                s[kk] = sum * ATTN_SCALE;
            }
            float tm = s[0];
            #pragma unroll
            for (int kk = 1; kk < 16; ++kk) tm = fmaxf(tm, s[kk]);
            const float mnew  = fmaxf(m, tm);
            const float alpha = __expf(m - mnew);
            l *= alpha;
            #pragma unroll
            for (int d = 0; d < 64; ++d) acc[d] *= alpha;
            #pragma unroll
            for (int kk = 0; kk < 16; ++kk) {
                const float p = __expf(s[kk] - mnew);
                l += p;
                const float4* vr = reinterpret_cast<const float4*>(
                    Vs + (c * 16 + kk) * 64);
                #pragma unroll
                for (int d4 = 0; d4 < 16; ++d4) {
                    float4 vv = vr[d4];
                    acc[4*d4+0] += p * vv.x;
                    acc[4*d4+1] += p * vv.y;
                    acc[4*d4+2] += p * vv.z;
                    acc[4*d4+3] += p * vv.w;
                }
            }
            m = mnew;
        }
        __syncthreads();
    }

    const float inv = 1.0f / l;
    const int b = bh >> 4, h = bh & 15;
    float* op = g_o + ((size_t)(b * NV + nq)) * CV + h * HDV;
    #pragma unroll
    for (int i = 0; i < 16; ++i) {
        float4 t;
        t.x = acc[4*i+0] * inv; t.y = acc[4*i+1] * inv;
        t.z = acc[4*i+2] * inv; t.w = acc[4*i+3] * inv;
        *reinterpret_cast<float4*>(op + 4 * i) = t;
    }
}

// ---------------------------------------------------------------------------
// Output projection: g_o[4096,1024] @ Wp[1024,1024] + bias -> out
// ---------------------------------------------------------------------------
__global__ __launch_bounds__(256) void proj_gemm_kernel(
    const float* __restrict__ Wp, const float* __restrict__ bias,
    float* __restrict__ out)
{
    __shared__ float As[16][64];
    __shared__ float Bs[16][64];

    const int tid = threadIdx.x;
    const int tx  = tid & 15;
    const int ty  = tid >> 4;
    const int c0  = blockIdx.x * 64;
    const int r0  = blockIdx.y * 64;
    const int K   = CV;
    const int Nc  = CV;

    const int am = tid >> 2;
    const int ak = (tid & 3) * 4;
    const int bk = tid >> 4;
    const int bc = (tid & 15) * 4;

    float acc[4][4] = {};

    for (int k0 = 0; k0 < K; k0 += 16) {
        float4 a4 = *reinterpret_cast<const float4*>(
            g_o + (size_t)(r0 + am) * K + k0 + ak);
        As[ak + 0][am] = a4.x;
        As[ak + 1][am] = a4.y;
        As[ak + 2][am] = a4.z;
        As[ak + 3][am] = a4.w;
        *reinterpret_cast<float4*>(&Bs[bk][bc]) =
            *reinterpret_cast<const float4*>(Wp + (size_t)(k0 + bk) * Nc + c0 + bc);
        __syncthreads();

        #pragma unroll
        for (int kk = 0; kk < 16; ++kk) {
            float4 av = *reinterpret_cast<const float4*>(&As[kk][ty * 4]);
            float4 bv = *reinterpret_cast<const float4*>(&Bs[kk][tx * 4]);
            acc[0][0] += av.x * bv.x; acc[0][1] += av.x * bv.y;
            acc[0][2] += av.x * bv.z; acc[0][3] += av.x * bv.w;
            acc[1][0] += av.y * bv.x; acc[1][1] += av.y * bv.y;
            acc[1][2] += av.y * bv.z; acc[1][3] += av.y * bv.w;
            acc[2][0] += av.z * bv.x; acc[2][1] += av.z * bv.y;
            acc[2][2] += av.z * bv.z; acc[2][3] += av.z * bv.w;
            acc[3][0] += av.w * bv.x; acc[3][1] += av.w * bv.y;
            acc[3][2] += av.w * bv.z; acc[3][3] += av.w * bv.w;
        }
        __syncthreads();
    }

    #pragma unroll
    for (int i = 0; i < 4; ++i) {
        const int row = r0 + ty * 4 + i;
        #pragma unroll
        for (int j = 0; j < 4; ++j) {
            const int col = c0 + tx * 4 + j;
            out[(size_t)row * Nc + col] = acc[i][j] + bias[col];
        }
    }
}

// ---------------------------------------------------------------------------
extern "C" void kernel_launch(void* const* d_in, const int* in_sizes, int n_in,
                              void* d_out, int out_size)
{
    const float* x      = (const float*)d_in[0];
    const float* w_qkv  = (const float*)d_in[1];
    const float* b_qkv  = (const float*)d_in[2];
    const float* a_q    = (const float*)d_in[3];
    const float* b_q    = (const float*)d_in[4];
    const float* a_v    = (const float*)d_in[5];
    const float* b_v    = (const float*)d_in[6];
    const float* w_proj = (const float*)d_in[7];
    const float* b_proj = (const float*)d_in[8];
    float* out = (float*)d_out;

    (void)in_sizes; (void)n_in; (void)out_size;

    // 1) QKV GEMM + bias -> g_q/g_k/g_v  [B,H,N,HD]
    qkv_gemm_kernel<<<dim3(3 * CV / 64, MROWS / 64), 256>>>(x, w_qkv, b_qkv);

    // 2) LoRA deltas on q and v
    lora_kernel<<<(BV * HV * NV) / 256, 256>>>(0, a_q, b_q);
    lora_kernel<<<(BV * HV * NV) / 256, 256>>>(1, a_v, b_v);

    // 3) attention -> g_o [B,N,C]
    flash_kernel<<<dim3(NV / 128, BV * HV), 128>>>();

    // 4) projection -> out
    proj_gemm_kernel<<<dim3(CV / 64, MROWS / 64), 256>>>(w_proj, b_proj, out);
}

// round 3
// speedup vs baseline: 1.4474x; 1.4474x over previous
#include <cuda_runtime.h>
#include <math.h>

// Problem constants
#define BV   2
#define NV   2048
#define CV   1024
#define HV   16
#define HDV  64
#define RV   16
#define MROWS (BV*NV)            // 4096
#define LORA_SCALE 2.0f
#define ATTN_SCALE 0.125f        // 64^-0.5

// Scratch (device globals — allocation-free per harness rules)
__device__ float g_q[(size_t)BV*HV*NV*HDV];   // [B,H,N,HD]
__device__ float g_k[(size_t)BV*HV*NV*HDV];
__device__ float g_v[(size_t)BV*HV*NV*HDV];
__device__ float g_o[(size_t)MROWS*CV];       // [B,N,C] attention output

// ---------------------------------------------------------------------------
// QKV GEMM: X[4096,1024] @ W[1024,3072] + bias, scatter into g_q/g_k/g_v
// ---------------------------------------------------------------------------
__global__ __launch_bounds__(256) void qkv_gemm_kernel(
    const float* __restrict__ X, const float* __restrict__ W,
    const float* __restrict__ bias)
{
    __shared__ float As[16][64];
    __shared__ float Bs[16][64];

    const int tid = threadIdx.x;
    const int tx  = tid & 15;
    const int ty  = tid >> 4;
    const int c0  = blockIdx.x * 64;
    const int r0  = blockIdx.y * 64;
    const int K   = CV;
    const int Nc  = 3 * CV;

    const int am = tid >> 2;
    const int ak = (tid & 3) * 4;
    const int bk = tid >> 4;
    const int bc = (tid & 15) * 4;

    float acc[4][4] = {};

    for (int k0 = 0; k0 < K; k0 += 16) {
        float4 a4 = *reinterpret_cast<const float4*>(
            X + (size_t)(r0 + am) * K + k0 + ak);
        As[ak + 0][am] = a4.x;
        As[ak + 1][am] = a4.y;
        As[ak + 2][am] = a4.z;
        As[ak + 3][am] = a4.w;
        *reinterpret_cast<float4*>(&Bs[bk][bc]) =
            *reinterpret_cast<const float4*>(W + (size_t)(k0 + bk) * Nc + c0 + bc);
        __syncthreads();

        #pragma unroll
        for (int kk = 0; kk < 16; ++kk) {
            float4 av = *reinterpret_cast<const float4*>(&As[kk][ty * 4]);
            float4 bv = *reinterpret_cast<const float4*>(&Bs[kk][tx * 4]);
            acc[0][0] += av.x * bv.x; acc[0][1] += av.x * bv.y;
            acc[0][2] += av.x * bv.z; acc[0][3] += av.x * bv.w;
            acc[1][0] += av.y * bv.x; acc[1][1] += av.y * bv.y;
            acc[1][2] += av.y * bv.z; acc[1][3] += av.y * bv.w;
            acc[2][0] += av.z * bv.x; acc[2][1] += av.z * bv.y;
            acc[2][2] += av.z * bv.z; acc[2][3] += av.z * bv.w;
            acc[3][0] += av.w * bv.x; acc[3][1] += av.w * bv.y;
            acc[3][2] += av.w * bv.z; acc[3][3] += av.w * bv.w;
        }
        __syncthreads();
    }

    #pragma unroll
    for (int i = 0; i < 4; ++i) {
        const int row = r0 + ty * 4 + i;
        const int b   = row >> 11;
        const int n   = row & 2047;
        #pragma unroll
        for (int j = 0; j < 4; ++j) {
            const int col   = c0 + tx * 4 + j;
            const float val = acc[i][j] + bias[col];
            const int which = col >> 10;
            const int rem   = col & 1023;
            const int h     = rem >> 6;
            const int d     = rem & 63;
            float* dst = (which == 0) ? g_q : (which == 1) ? g_k : g_v;
            dst[(((size_t)(b * HV + h) * NV) + n) * HDV + d] = val;
        }
    }
}

// ---------------------------------------------------------------------------
// LoRA: row += 2 * ((row @ A[64,16]) @ Bm[16,64]), one thread per head-row.
// ---------------------------------------------------------------------------
__global__ __launch_bounds__(256) void lora_kernel(
    int which, const float* __restrict__ A, const float* __restrict__ Bm)
{
    __shared__ float sA[HDV * RV];
    __shared__ float sB[RV * HDV];
    const int tid = threadIdx.x;
    #pragma unroll
    for (int i = 0; i < 4; ++i) {
        sA[tid + i * 256] = A[tid + i * 256];
        sB[tid + i * 256] = Bm[tid + i * 256];
    }
    __syncthreads();

    float* data = which ? g_v : g_q;
    const size_t row = (size_t)blockIdx.x * 256 + tid;
    float* p = data + row * HDV;

    float xv[64];
    #pragma unroll
    for (int i = 0; i < 16; ++i) {
        float4 t = *reinterpret_cast<const float4*>(p + 4 * i);
        xv[4*i+0] = t.x; xv[4*i+1] = t.y; xv[4*i+2] = t.z; xv[4*i+3] = t.w;
    }

    float r[16] = {};
    #pragma unroll
    for (int d = 0; d < 64; ++d) {
        #pragma unroll
        for (int j = 0; j < 16; ++j)
            r[j] += xv[d] * sA[d * RV + j];
    }

    #pragma unroll
    for (int i = 0; i < 16; ++i) {
        float4 t;
        float o[4];
        #pragma unroll
        for (int q = 0; q < 4; ++q) {
            const int d = 4 * i + q;
            float delta = 0.f;
            #pragma unroll
            for (int j = 0; j < 16; ++j)
                delta += r[j] * sB[j * HDV + d];
            o[q] = xv[d] + LORA_SCALE * delta;
        }
        t.x = o[0]; t.y = o[1]; t.z = o[2]; t.w = o[3];
        *reinterpret_cast<float4*>(p + 4 * i) = t;
    }
}

// ---------------------------------------------------------------------------
// Flash attention (fp32), split-d: a LANE PAIR owns one query row.
//   thread (lane even)  -> dims [0,32)
//   thread (lane odd)   -> dims [32,64)
// Score dot completed with one __shfl_xor. Registers: qr[32]+acc[32] -> no
// spills. K/V tiles (64 keys) live in smem with the two 32-float halves
// interleaved at float4 granularity so a pair's LDS.128 covers one
// contiguous 32B region (single wavefront, no bank conflict).
// grid: (N/128, B*H), block: 256 (128 queries)
// ---------------------------------------------------------------------------
__global__ __launch_bounds__(256) void flash_kernel()
{
    // physical f4 index = key*16 + (d4 & 7)*2 + (d4 >> 3)
    __shared__ float4 Ks[64 * 16];
    __shared__ float4 Vs[64 * 16];

    const int tid  = threadIdx.x;
    const int half = tid & 1;                  // which 32-dim half
    const int qi   = tid >> 1;                 // 0..127 query within block
    const int bh   = blockIdx.y;               // 0..31
    const int nq   = blockIdx.x * 128 + qi;

    const float* qp = g_q + ((size_t)bh * NV + nq) * HDV + half * 32;
    float qr[32];
    #pragma unroll
    for (int i = 0; i < 8; ++i) {
        float4 t = *reinterpret_cast<const float4*>(qp + 4 * i);
        qr[4*i+0] = t.x; qr[4*i+1] = t.y; qr[4*i+2] = t.z; qr[4*i+3] = t.w;
    }

    float m = -INFINITY, l = 0.f;
    float acc[32] = {};

    for (int kt = 0; kt < NV / 64; ++kt) {
        const float4* kp = reinterpret_cast<const float4*>(
            g_k + ((size_t)bh * NV + kt * 64) * HDV);
        const float4* vp = reinterpret_cast<const float4*>(
            g_v + ((size_t)bh * NV + kt * 64) * HDV);
        #pragma unroll
        for (int i = 0; i < 4; ++i) {
            const int idx = tid + i * 256;     // 0..1023 source f4 (key*16+d4)
            const int key = idx >> 4;
            const int d4  = idx & 15;
            const int dst = key * 16 + ((d4 & 7) << 1) + (d4 >> 3);
            Ks[dst] = kp[idx];
            Vs[dst] = vp[idx];
        }
        __syncthreads();

        #pragma unroll
        for (int c = 0; c < 4; ++c) {
            float s[16];
            #pragma unroll
            for (int kk = 0; kk < 16; ++kk) {
                const float4* kr = &Ks[(c * 16 + kk) * 16 + half];
                float sum = 0.f;
                #pragma unroll
                for (int d4 = 0; d4 < 8; ++d4) {
                    float4 kv = kr[d4 * 2];
                    sum += qr[4*d4+0] * kv.x + qr[4*d4+1] * kv.y
                         + qr[4*d4+2] * kv.z + qr[4*d4+3] * kv.w;
                }
                sum += __shfl_xor_sync(0xffffffff, sum, 1);
                s[kk] = sum * ATTN_SCALE;
            }
            float tm = s[0];
            #pragma unroll
            for (int kk = 1; kk < 16; ++kk) tm = fmaxf(tm, s[kk]);
            const float mnew  = fmaxf(m, tm);
            const float alpha = __expf(m - mnew);
            l *= alpha;
            #pragma unroll
            for (int d = 0; d < 32; ++d) acc[d] *= alpha;
            #pragma unroll
            for (int kk = 0; kk < 16; ++kk) {
                const float p = __expf(s[kk] - mnew);
                l += p;
                const float4* vr = &Vs[(c * 16 + kk) * 16 + half];
                #pragma unroll
                for (int d4 = 0; d4 < 8; ++d4) {
                    float4 vv = vr[d4 * 2];
                    acc[4*d4+0] += p * vv.x;
                    acc[4*d4+1] += p * vv.y;
                    acc[4*d4+2] += p * vv.z;
                    acc[4*d4+3] += p * vv.w;
                }
            }
            m = mnew;
        }
        __syncthreads();
    }

    const float inv = 1.0f / l;
    const int b = bh >> 4, h = bh & 15;
    float* op = g_o + ((size_t)(b * NV + nq)) * CV + h * HDV + half * 32;
    #pragma unroll
    for (int i = 0; i < 8; ++i) {
        float4 t;
        t.x = acc[4*i+0] * inv; t.y = acc[4*i+1] * inv;
        t.z = acc[4*i+2] * inv; t.w = acc[4*i+3] * inv;
        *reinterpret_cast<float4*>(op + 4 * i) = t;
    }
}

// ---------------------------------------------------------------------------
// Output projection: g_o[4096,1024] @ Wp[1024,1024] + bias -> out
// ---------------------------------------------------------------------------
__global__ __launch_bounds__(256) void proj_gemm_kernel(
    const float* __restrict__ Wp, const float* __restrict__ bias,
    float* __restrict__ out)
{
    __shared__ float As[16][64];
    __shared__ float Bs[16][64];

    const int tid = threadIdx.x;
    const int tx  = tid & 15;
    const int ty  = tid >> 4;
    const int c0  = blockIdx.x * 64;
    const int r0  = blockIdx.y * 64;
    const int K   = CV;
    const int Nc  = CV;

    const int am = tid >> 2;
    const int ak = (tid & 3) * 4;
    const int bk = tid >> 4;
    const int bc = (tid & 15) * 4;

    float acc[4][4] = {};

    for (int k0 = 0; k0 < K; k0 += 16) {
        float4 a4 = *reinterpret_cast<const float4*>(
            g_o + (size_t)(r0 + am) * K + k0 + ak);
        As[ak + 0][am] = a4.x;
        As[ak + 1][am] = a4.y;
        As[ak + 2][am] = a4.z;
        As[ak + 3][am] = a4.w;
        *reinterpret_cast<float4*>(&Bs[bk][bc]) =
            *reinterpret_cast<const float4*>(Wp + (size_t)(k0 + bk) * Nc + c0 + bc);
        __syncthreads();

        #pragma unroll
        for (int kk = 0; kk < 16; ++kk) {
            float4 av = *reinterpret_cast<const float4*>(&As[kk][ty * 4]);
            float4 bv = *reinterpret_cast<const float4*>(&Bs[kk][tx * 4]);
            acc[0][0] += av.x * bv.x; acc[0][1] += av.x * bv.y;
            acc[0][2] += av.x * bv.z; acc[0][3] += av.x * bv.w;
            acc[1][0] += av.y * bv.x; acc[1][1] += av.y * bv.y;
            acc[1][2] += av.y * bv.z; acc[1][3] += av.y * bv.w;
            acc[2][0] += av.z * bv.x; acc[2][1] += av.z * bv.y;
            acc[2][2] += av.z * bv.z; acc[2][3] += av.z * bv.w;
            acc[3][0] += av.w * bv.x; acc[3][1] += av.w * bv.y;
            acc[3][2] += av.w * bv.z; acc[3][3] += av.w * bv.w;
        }
        __syncthreads();
    }

    #pragma unroll
    for (int i = 0; i < 4; ++i) {
        const int row = r0 + ty * 4 + i;
        #pragma unroll
        for (int j = 0; j < 4; ++j) {
            const int col = c0 + tx * 4 + j;
            out[(size_t)row * Nc + col] = acc[i][j] + bias[col];
        }
    }
}

// ---------------------------------------------------------------------------
extern "C" void kernel_launch(void* const* d_in, const int* in_sizes, int n_in,
                              void* d_out, int out_size)
{
    const float* x      = (const float*)d_in[0];
    const float* w_qkv  = (const float*)d_in[1];
    const float* b_qkv  = (const float*)d_in[2];
    const float* a_q    = (const float*)d_in[3];
    const float* b_q    = (const float*)d_in[4];
    const float* a_v    = (const float*)d_in[5];
    const float* b_v    = (const float*)d_in[6];
    const float* w_proj = (const float*)d_in[7];
    const float* b_proj = (const float*)d_in[8];
    float* out = (float*)d_out;

    (void)in_sizes; (void)n_in; (void)out_size;

    qkv_gemm_kernel<<<dim3(3 * CV / 64, MROWS / 64), 256>>>(x, w_qkv, b_qkv);
    lora_kernel<<<(BV * HV * NV) / 256, 256>>>(0, a_q, b_q);
    lora_kernel<<<(BV * HV * NV) / 256, 256>>>(1, a_v, b_v);
    flash_kernel<<<dim3(NV / 128, BV * HV), 256>>>();
    proj_gemm_kernel<<<dim3(CV / 64, MROWS / 64), 256>>>(w_proj, b_proj, out);
}

// round 4
// speedup vs baseline: 3.8512x; 2.6608x over previous
#include <cuda_runtime.h>
#include <cuda_bf16.h>
#include <math.h>
#include <stdint.h>

// Problem constants
#define BV   2
#define NV   2048
#define CV   1024
#define HV   16
#define HDV  64
#define MROWS (BV*NV)            // 4096
#define LORA_SCALE 2.0f
#define SM_SCALE 0.1803368801f   // 64^-0.5 * log2(e)

#define BHND ((size_t)BV*HV*NV*HDV)

// fp32 scratch
__device__ float g_q[BHND];
__device__ float g_k[BHND];
__device__ float g_v[BHND];
__device__ float g_o[(size_t)MROWS*CV];
// split-bf16 scratch (hi + lo, lo = residual)
__device__ __nv_bfloat16 g_qh[BHND], g_ql[BHND];
__device__ __nv_bfloat16 g_kh[BHND], g_kl[BHND];
__device__ __nv_bfloat16 g_vh[BHND], g_vl[BHND];

// ---------------------------------------------------------------------------
// helpers
// ---------------------------------------------------------------------------
__device__ __forceinline__ void ldsm4(uint32_t r[4], const void* p) {
    uint32_t a = (uint32_t)__cvta_generic_to_shared(p);
    asm volatile("ldmatrix.sync.aligned.m8n8.x4.shared.b16 {%0,%1,%2,%3},[%4];"
        : "=r"(r[0]), "=r"(r[1]), "=r"(r[2]), "=r"(r[3]) : "r"(a));
}
__device__ __forceinline__ void ldsm4t(uint32_t r[4], const void* p) {
    uint32_t a = (uint32_t)__cvta_generic_to_shared(p);
    asm volatile("ldmatrix.sync.aligned.m8n8.x4.trans.shared.b16 {%0,%1,%2,%3},[%4];"
        : "=r"(r[0]), "=r"(r[1]), "=r"(r[2]), "=r"(r[3]) : "r"(a));
}
__device__ __forceinline__ void mma_bf16(float d[4],
    uint32_t a0, uint32_t a1, uint32_t a2, uint32_t a3,
    uint32_t b0, uint32_t b1)
{
    asm volatile(
        "mma.sync.aligned.m16n8k16.row.col.f32.bf16.bf16.f32 "
        "{%0,%1,%2,%3},{%4,%5,%6,%7},{%8,%9},{%0,%1,%2,%3};"
        : "+f"(d[0]), "+f"(d[1]), "+f"(d[2]), "+f"(d[3])
        : "r"(a0), "r"(a1), "r"(a2), "r"(a3), "r"(b0), "r"(b1));
}
__device__ __forceinline__ float ex2f(float x) {
    float r; asm("ex2.approx.ftz.f32 %0,%1;" : "=f"(r) : "f"(x)); return r;
}
// split fp32 pair -> packed bf16 hi / lo
__device__ __forceinline__ void packsplit(float x, float y,
                                          uint32_t& hp, uint32_t& lp)
{
    __nv_bfloat162 h = __floats2bfloat162_rn(x, y);
    __nv_bfloat162 l = __floats2bfloat162_rn(x - __bfloat162float(h.x),
                                             y - __bfloat162float(h.y));
    hp = *reinterpret_cast<uint32_t*>(&h);
    lp = *reinterpret_cast<uint32_t*>(&l);
}
// split a float4 into hi/lo bf16, store 4 consecutive elements to smem
__device__ __forceinline__ void split_store4(__nv_bfloat16* H, __nv_bfloat16* L,
                                             int off, float4 v)
{
    __nv_bfloat162 h0 = __floats2bfloat162_rn(v.x, v.y);
    __nv_bfloat162 h1 = __floats2bfloat162_rn(v.z, v.w);
    __nv_bfloat162 l0 = __floats2bfloat162_rn(v.x - __bfloat162float(h0.x),
                                              v.y - __bfloat162float(h0.y));
    __nv_bfloat162 l1 = __floats2bfloat162_rn(v.z - __bfloat162float(h1.x),
                                              v.w - __bfloat162float(h1.y));
    *reinterpret_cast<__nv_bfloat162*>(H + off)     = h0;
    *reinterpret_cast<__nv_bfloat162*>(H + off + 2) = h1;
    *reinterpret_cast<__nv_bfloat162*>(L + off)     = l0;
    *reinterpret_cast<__nv_bfloat162*>(L + off + 2) = l1;
}

__device__ __forceinline__ void qkv_scatter(int row, int col, float val) {
    const int b = row >> 11, n = row & 2047;
    const int which = col >> 10, rem = col & 1023;
    const int h = rem >> 6, d = rem & 63;
    float* dst = (which == 0) ? g_q : (which == 1) ? g_k : g_v;
    dst[(((size_t)(b * HV + h)) * NV + n) * HDV + d] = val;
}

// ---------------------------------------------------------------------------
// Generic split-bf16 GEMM: C[M,*] = A[M,1024] @ B[1024,Ncols] + bias
// Block tile 128x128, K-step 32, 8 warps (2x4 of 64x32 warp tiles).
// mode 0: scatter into g_q/g_k/g_v (QKV).  mode 1: plain store to Cout.
// Ain == nullptr -> A = g_o.
// ---------------------------------------------------------------------------
__global__ __launch_bounds__(256) void gemm3_kernel(
    const float* __restrict__ Ain, const float* __restrict__ B,
    const float* __restrict__ bias, float* __restrict__ Cout,
    int Ncols, int mode)
{
    __shared__ __nv_bfloat16 sAh[128 * 40], sAl[128 * 40];
    __shared__ __nv_bfloat16 sBh[32 * 136], sBl[32 * 136];

    const float* A = Ain ? Ain : g_o;
    const int tid  = threadIdx.x;
    const int lane = tid & 31;
    const int warp = tid >> 5;
    const int m0   = (warp >> 2) * 64;
    const int n0   = (warp & 3) * 32;
    const int rB   = blockIdx.y * 128;
    const int cB   = blockIdx.x * 128;

    float acc[4][4][4];
    #pragma unroll
    for (int i = 0; i < 4; ++i)
        #pragma unroll
        for (int j = 0; j < 4; ++j)
            #pragma unroll
            for (int r = 0; r < 4; ++r) acc[i][j][r] = 0.f;

    const int arow = tid >> 3, acol = (tid & 7) * 4;
    const int brow = tid >> 5, bcol = (tid & 31) * 4;

    for (int k0 = 0; k0 < 1024; k0 += 32) {
        __syncthreads();
        #pragma unroll
        for (int i = 0; i < 4; ++i) {
            const int r = arow + i * 32;
            float4 v = *reinterpret_cast<const float4*>(
                A + (size_t)(rB + r) * 1024 + k0 + acol);
            split_store4(sAh, sAl, r * 40 + acol, v);
        }
        #pragma unroll
        for (int i = 0; i < 4; ++i) {
            const int r = brow + i * 8;
            float4 v = *reinterpret_cast<const float4*>(
                B + (size_t)(k0 + r) * Ncols + cB + bcol);
            split_store4(sBh, sBl, r * 136 + bcol, v);
        }
        __syncthreads();

        #pragma unroll
        for (int ks = 0; ks < 2; ++ks) {
            uint32_t ah[4][4], al[4][4];
            #pragma unroll
            for (int mi = 0; mi < 4; ++mi) {
                const int off = (m0 + mi * 16 + (lane & 15)) * 40
                              + ks * 16 + ((lane >> 4) << 3);
                ldsm4(ah[mi], sAh + off);
                ldsm4(al[mi], sAl + off);
            }
            uint32_t bh[4][2], bl[4][2];
            #pragma unroll
            for (int Jp = 0; Jp < 2; ++Jp) {
                const int off = (ks * 16 + (lane & 15)) * 136
                              + n0 + Jp * 16 + ((lane >> 4) << 3);
                uint32_t t[4];
                ldsm4t(t, sBh + off);
                bh[2*Jp][0] = t[0]; bh[2*Jp][1] = t[1];
                bh[2*Jp+1][0] = t[2]; bh[2*Jp+1][1] = t[3];
                ldsm4t(t, sBl + off);
                bl[2*Jp][0] = t[0]; bl[2*Jp][1] = t[1];
                bl[2*Jp+1][0] = t[2]; bl[2*Jp+1][1] = t[3];
            }
            #pragma unroll
            for (int mi = 0; mi < 4; ++mi)
                #pragma unroll
                for (int nj = 0; nj < 4; ++nj) {
                    mma_bf16(acc[mi][nj], ah[mi][0], ah[mi][1], ah[mi][2], ah[mi][3],
                             bh[nj][0], bh[nj][1]);
                    mma_bf16(acc[mi][nj], ah[mi][0], ah[mi][1], ah[mi][2], ah[mi][3],
                             bl[nj][0], bl[nj][1]);
                    mma_bf16(acc[mi][nj], al[mi][0], al[mi][1], al[mi][2], al[mi][3],
                             bh[nj][0], bh[nj][1]);
                }
        }
    }

    const int g  = lane >> 2;
    const int t2 = (lane & 3) * 2;
    #pragma unroll
    for (int mi = 0; mi < 4; ++mi)
        #pragma unroll
        for (int nj = 0; nj < 4; ++nj) {
            const int r = rB + m0 + mi * 16 + g;
            const int c = cB + n0 + nj * 8 + t2;
            const float b0 = bias[c], b1 = bias[c + 1];
            const float v00 = acc[mi][nj][0] + b0;
            const float v01 = acc[mi][nj][1] + b1;
            const float v10 = acc[mi][nj][2] + b0;
            const float v11 = acc[mi][nj][3] + b1;
            if (mode == 1) {
                Cout[(size_t)r * Ncols + c]           = v00;
                Cout[(size_t)r * Ncols + c + 1]       = v01;
                Cout[(size_t)(r + 8) * Ncols + c]     = v10;
                Cout[(size_t)(r + 8) * Ncols + c + 1] = v11;
            } else {
                qkv_scatter(r,     c,     v00);
                qkv_scatter(r,     c + 1, v01);
                qkv_scatter(r + 8, c,     v10);
                qkv_scatter(r + 8, c + 1, v11);
            }
        }
}

// ---------------------------------------------------------------------------
// post-QKV: apply LoRA delta (which=0: q, which=1: v) or just convert (2: k),
// then write split bf16 hi/lo. One thread per head-row.
// ---------------------------------------------------------------------------
__global__ __launch_bounds__(256) void postqkv_kernel(
    int which, const float* __restrict__ A, const float* __restrict__ Bm)
{
    __shared__ float sA[HDV * 16];
    __shared__ float sB[16 * HDV];
    const int tid = threadIdx.x;
    if (which != 2) {
        #pragma unroll
        for (int i = 0; i < 4; ++i) {
            sA[tid + i * 256] = A[tid + i * 256];
            sB[tid + i * 256] = Bm[tid + i * 256];
        }
    }
    __syncthreads();

    const float* src = (which == 0) ? g_q : (which == 1) ? g_v : g_k;
    __nv_bfloat16* dh = (which == 0) ? g_qh : (which == 1) ? g_vh : g_kh;
    __nv_bfloat16* dl = (which == 0) ? g_ql : (which == 1) ? g_vl : g_kl;

    const size_t row = (size_t)blockIdx.x * 256 + tid;
    const float* p = src + row * HDV;

    float xv[64];
    #pragma unroll
    for (int i = 0; i < 16; ++i) {
        float4 t = *reinterpret_cast<const float4*>(p + 4 * i);
        xv[4*i+0] = t.x; xv[4*i+1] = t.y; xv[4*i+2] = t.z; xv[4*i+3] = t.w;
    }

    if (which != 2) {
        float r[16] = {};
        #pragma unroll
        for (int d = 0; d < 64; ++d)
            #pragma unroll
            for (int j = 0; j < 16; ++j)
                r[j] += xv[d] * sA[d * 16 + j];
        #pragma unroll
        for (int d = 0; d < 64; ++d) {
            float delta = 0.f;
            #pragma unroll
            for (int j = 0; j < 16; ++j)
                delta += r[j] * sB[j * 64 + d];
            xv[d] += LORA_SCALE * delta;
        }
    }

    #pragma unroll
    for (int i = 0; i < 32; ++i) {
        const float x = xv[2*i], y = xv[2*i+1];
        __nv_bfloat162 h = __floats2bfloat162_rn(x, y);
        __nv_bfloat162 l = __floats2bfloat162_rn(x - __bfloat162float(h.x),
                                                 y - __bfloat162float(h.y));
        *reinterpret_cast<__nv_bfloat162*>(dh + row * 64 + 2*i) = h;
        *reinterpret_cast<__nv_bfloat162*>(dl + row * 64 + 2*i) = l;
    }
}

// ---------------------------------------------------------------------------
// Flash attention on tensor cores (split-bf16 x3 for QK^T and PV).
// Block: 128 queries, 8 warps x 16 rows. Loop over 32 key tiles of 64.
// grid (N/128, B*H) = (16, 32), 256 threads.
// ---------------------------------------------------------------------------
__global__ __launch_bounds__(256) void flash_mma_kernel()
{
    // 18432 halves: Q stage = [Qh(9216) | Ql(9216)], then reused as
    // [Kh(4608) | Kl | Vh | Vl], rows padded to 72 halves.
    __shared__ __nv_bfloat16 sbuf[4 * 64 * 72];
    __nv_bfloat16* Kh = sbuf;
    __nv_bfloat16* Kl = sbuf + 4608;
    __nv_bfloat16* Vh = sbuf + 9216;
    __nv_bfloat16* Vl = sbuf + 13824;

    const int tid  = threadIdx.x;
    const int lane = tid & 31;
    const int w    = tid >> 5;
    const int bh   = blockIdx.y;
    const int b    = bh >> 4, h = bh & 15;
    const int q0   = blockIdx.x * 128;
    const size_t base = (size_t)bh * NV * 64;

    // stage Q hi/lo (128 x 64 halves each)
    {
        const uint4* gh = reinterpret_cast<const uint4*>(g_qh + base + (size_t)q0 * 64);
        const uint4* gl = reinterpret_cast<const uint4*>(g_ql + base + (size_t)q0 * 64);
        #pragma unroll
        for (int i = 0; i < 4; ++i) {
            const int idx = tid + i * 256;         // 0..1023 uint4
            const int row = idx >> 3, col8 = (idx & 7) * 8;
            *reinterpret_cast<uint4*>(&sbuf[row * 72 + col8])        = gh[idx];
            *reinterpret_cast<uint4*>(&sbuf[9216 + row * 72 + col8]) = gl[idx];
        }
    }
    __syncthreads();

    // Q fragments (persistent)
    uint32_t qh[4][4], ql[4][4];
    #pragma unroll
    for (int kk = 0; kk < 4; ++kk) {
        const int off = (w * 16 + (lane & 15)) * 72
                      + kk * 16 + ((lane >> 4) << 3);
        ldsm4(qh[kk], sbuf + off);
        ldsm4(ql[kk], sbuf + 9216 + off);
    }

    float m0 = -1e30f, m1 = -1e30f, l0 = 0.f, l1 = 0.f;
    float acc[8][4];
    #pragma unroll
    for (int j = 0; j < 8; ++j)
        #pragma unroll
        for (int r = 0; r < 4; ++r) acc[j][r] = 0.f;

    const uint4* gkh = reinterpret_cast<const uint4*>(g_kh + base);
    const uint4* gkl = reinterpret_cast<const uint4*>(g_kl + base);
    const uint4* gvh = reinterpret_cast<const uint4*>(g_vh + base);
    const uint4* gvl = reinterpret_cast<const uint4*>(g_vl + base);

    for (int kt = 0; kt < NV / 64; ++kt) {
        __syncthreads();
        #pragma unroll
        for (int i = 0; i < 2; ++i) {
            const int idx = tid + i * 256;       // 0..511 uint4 per array
            const int row = idx >> 3, col8 = (idx & 7) * 8;
            const int soff = row * 72 + col8;
            const int goff = kt * 512 + idx;
            *reinterpret_cast<uint4*>(&Kh[soff]) = gkh[goff];
            *reinterpret_cast<uint4*>(&Kl[soff]) = gkl[goff];
            *reinterpret_cast<uint4*>(&Vh[soff]) = gvh[goff];
            *reinterpret_cast<uint4*>(&Vl[soff]) = gvl[goff];
        }
        __syncthreads();

        // S = Q K^T  (16 rows x 64 keys per warp)
        float s[8][4];
        #pragma unroll
        for (int j = 0; j < 8; ++j)
            #pragma unroll
            for (int r = 0; r < 4; ++r) s[j][r] = 0.f;

        #pragma unroll
        for (int kk = 0; kk < 4; ++kk) {
            #pragma unroll
            for (int J = 0; J < 4; ++J) {
                const int keyrow = J * 16 + (lane & 7) + ((lane >> 4) << 3);
                const int dim    = kk * 16 + (((lane >> 3) & 1) << 3);
                const int off    = keyrow * 72 + dim;
                uint32_t kbh[4], kbl[4];
                ldsm4(kbh, Kh + off);
                ldsm4(kbl, Kl + off);
                mma_bf16(s[2*J],   qh[kk][0], qh[kk][1], qh[kk][2], qh[kk][3], kbh[0], kbh[1]);
                mma_bf16(s[2*J],   qh[kk][0], qh[kk][1], qh[kk][2], qh[kk][3], kbl[0], kbl[1]);
                mma_bf16(s[2*J],   ql[kk][0], ql[kk][1], ql[kk][2], ql[kk][3], kbh[0], kbh[1]);
                mma_bf16(s[2*J+1], qh[kk][0], qh[kk][1], qh[kk][2], qh[kk][3], kbh[2], kbh[3]);
                mma_bf16(s[2*J+1], qh[kk][0], qh[kk][1], qh[kk][2], qh[kk][3], kbl[2], kbl[3]);
                mma_bf16(s[2*J+1], ql[kk][0], ql[kk][1], ql[kk][2], ql[kk][3], kbh[2], kbh[3]);
            }
        }

        // online softmax (log2 domain)
        float mx0 = -1e30f, mx1 = -1e30f;
        #pragma unroll
        for (int j = 0; j < 8; ++j) {
            #pragma unroll
            for (int r = 0; r < 4; ++r) s[j][r] *= SM_SCALE;
            mx0 = fmaxf(mx0, fmaxf(s[j][0], s[j][1]));
            mx1 = fmaxf(mx1, fmaxf(s[j][2], s[j][3]));
        }
        mx0 = fmaxf(mx0, __shfl_xor_sync(0xffffffffu, mx0, 1));
        mx0 = fmaxf(mx0, __shfl_xor_sync(0xffffffffu, mx0, 2));
        mx1 = fmaxf(mx1, __shfl_xor_sync(0xffffffffu, mx1, 1));
        mx1 = fmaxf(mx1, __shfl_xor_sync(0xffffffffu, mx1, 2));
        const float mn0 = fmaxf(m0, mx0), mn1 = fmaxf(m1, mx1);
        const float al0 = ex2f(m0 - mn0), al1 = ex2f(m1 - mn1);
        l0 *= al0; l1 *= al1;
        #pragma unroll
        for (int j = 0; j < 8; ++j) {
            acc[j][0] *= al0; acc[j][1] *= al0;
            acc[j][2] *= al1; acc[j][3] *= al1;
            s[j][0] = ex2f(s[j][0] - mn0);
            s[j][1] = ex2f(s[j][1] - mn0);
            s[j][2] = ex2f(s[j][2] - mn1);
            s[j][3] = ex2f(s[j][3] - mn1);
            l0 += s[j][0] + s[j][1];
            l1 += s[j][2] + s[j][3];
        }
        m0 = mn0; m1 = mn1;

        // acc += P V   (P converted D-frag -> A-frag in-register)
        #pragma unroll
        for (int kk = 0; kk < 4; ++kk) {
            uint32_t pah[4], pal[4];
            packsplit(s[2*kk][0],   s[2*kk][1],   pah[0], pal[0]);
            packsplit(s[2*kk][2],   s[2*kk][3],   pah[1], pal[1]);
            packsplit(s[2*kk+1][0], s[2*kk+1][1], pah[2], pal[2]);
            packsplit(s[2*kk+1][2], s[2*kk+1][3], pah[3], pal[3]);
            #pragma unroll
            for (int J = 0; J < 4; ++J) {
                const int key = kk * 16 + (lane & 15);
                const int dim = J * 16 + ((lane >> 4) << 3);
                const int off = key * 72 + dim;
                uint32_t vbh[4], vbl[4];
                ldsm4t(vbh, Vh + off);
                ldsm4t(vbl, Vl + off);
                mma_bf16(acc[2*J],   pah[0], pah[1], pah[2], pah[3], vbh[0], vbh[1]);
                mma_bf16(acc[2*J],   pah[0], pah[1], pah[2], pah[3], vbl[0], vbl[1]);
                mma_bf16(acc[2*J],   pal[0], pal[1], pal[2], pal[3], vbh[0], vbh[1]);
                mma_bf16(acc[2*J+1], pah[0], pah[1], pah[2], pah[3], vbh[2], vbh[3]);
                mma_bf16(acc[2*J+1], pah[0], pah[1], pah[2], pah[3], vbl[2], vbl[3]);
                mma_bf16(acc[2*J+1], pal[0], pal[1], pal[2], pal[3], vbh[2], vbh[3]);
            }
        }
    }

    l0 += __shfl_xor_sync(0xffffffffu, l0, 1);
    l0 += __shfl_xor_sync(0xffffffffu, l0, 2);
    l1 += __shfl_xor_sync(0xffffffffu, l1, 1);
    l1 += __shfl_xor_sync(0xffffffffu, l1, 2);
    const float inv0 = 1.f / l0, inv1 = 1.f / l1;

    const int g  = lane >> 2;
    const int t2 = (lane & 3) * 2;
    const int row0 = q0 + w * 16 + g;
    const size_t ob = ((size_t)b * NV + row0) * CV + h * 64;
    #pragma unroll
    for (int j = 0; j < 8; ++j) {
        const int c = j * 8 + t2;
        *reinterpret_cast<float2*>(&g_o[ob + c]) =
            make_float2(acc[j][0] * inv0, acc[j][1] * inv0);
        *reinterpret_cast<float2*>(&g_o[ob + (size_t)8 * CV + c]) =
            make_float2(acc[j][2] * inv1, acc[j][3] * inv1);
    }
}

// ---------------------------------------------------------------------------
extern "C" void kernel_launch(void* const* d_in, const int* in_sizes, int n_in,
                              void* d_out, int out_size)
{
    const float* x      = (const float*)d_in[0];
    const float* w_qkv  = (const float*)d_in[1];
    const float* b_qkv  = (const float*)d_in[2];
    const float* a_q    = (const float*)d_in[3];
    const float* b_q    = (const float*)d_in[4];
    const float* a_v    = (const float*)d_in[5];
    const float* b_v    = (const float*)d_in[6];
    const float* w_proj = (const float*)d_in[7];
    const float* b_proj = (const float*)d_in[8];
    float* out = (float*)d_out;

    (void)in_sizes; (void)n_in; (void)out_size;

    // 1) QKV GEMM (split-bf16 tensor cores) -> g_q/g_k/g_v fp32
    gemm3_kernel<<<dim3(3 * CV / 128, MROWS / 128), 256>>>(
        x, w_qkv, b_qkv, out, 3 * CV, 0);

    // 2) LoRA (q, v) + split-bf16 conversion; k convert-only
    postqkv_kernel<<<(BV * HV * NV) / 256, 256>>>(0, a_q, b_q);
    postqkv_kernel<<<(BV * HV * NV) / 256, 256>>>(1, a_v, b_v);
    postqkv_kernel<<<(BV * HV * NV) / 256, 256>>>(2, nullptr, nullptr);

    // 3) attention (tensor cores) -> g_o fp32
    flash_mma_kernel<<<dim3(NV / 128, BV * HV), 256>>>();

    // 4) projection (split-bf16 tensor cores) -> out
    gemm3_kernel<<<dim3(CV / 128, MROWS / 128), 256>>>(
        nullptr, w_proj, b_proj, out, CV, 1);
}

// round 8
// speedup vs baseline: 4.9149x; 1.2762x over previous
#include <cuda_runtime.h>
#include <cuda_bf16.h>
#include <math.h>
#include <stdint.h>

// Problem constants
#define BV   2
#define NV   2048
#define CV   1024
#define HV   16
#define HDV  64
#define MROWS (BV*NV)            // 4096
#define SM_SCALE 0.1803368801f   // 64^-0.5 * log2(e)

#define BHND ((size_t)BV*HV*NV*HDV)

// scratch
__device__ float g_o[(size_t)MROWS*CV];           // attention output fp32
__device__ float g_w2[(size_t)CV*3*CV];           // LoRA-folded QKV weight
__device__ float g_b2[3*CV];                      // LoRA-folded QKV bias
// split-bf16 q/k/v (hi + lo residual), layout [B,H,N,HD]
__device__ __nv_bfloat16 g_qh[BHND], g_ql[BHND];
__device__ __nv_bfloat16 g_kh[BHND], g_kl[BHND];
__device__ __nv_bfloat16 g_vh[BHND], g_vl[BHND];

// ---------------------------------------------------------------------------
// helpers
// ---------------------------------------------------------------------------
__device__ __forceinline__ void ldsm4(uint32_t r[4], const void* p) {
    uint32_t a = (uint32_t)__cvta_generic_to_shared(p);
    asm volatile("ldmatrix.sync.aligned.m8n8.x4.shared.b16 {%0,%1,%2,%3},[%4];"
        : "=r"(r[0]), "=r"(r[1]), "=r"(r[2]), "=r"(r[3]) : "r"(a));
}
__device__ __forceinline__ void ldsm4t(uint32_t r[4], const void* p) {
    uint32_t a = (uint32_t)__cvta_generic_to_shared(p);
    asm volatile("ldmatrix.sync.aligned.m8n8.x4.trans.shared.b16 {%0,%1,%2,%3},[%4];"
        : "=r"(r[0]), "=r"(r[1]), "=r"(r[2]), "=r"(r[3]) : "r"(a));
}
__device__ __forceinline__ void mma_bf16(float d[4],
    uint32_t a0, uint32_t a1, uint32_t a2, uint32_t a3,
    uint32_t b0, uint32_t b1)
{
    asm volatile(
        "mma.sync.aligned.m16n8k16.row.col.f32.bf16.bf16.f32 "
        "{%0,%1,%2,%3},{%4,%5,%6,%7},{%8,%9},{%0,%1,%2,%3};"
        : "+f"(d[0]), "+f"(d[1]), "+f"(d[2]), "+f"(d[3])
        : "r"(a0), "r"(a1), "r"(a2), "r"(a3), "r"(b0), "r"(b1));
}
__device__ __forceinline__ float ex2f(float x) {
    float r; asm("ex2.approx.ftz.f32 %0,%1;" : "=f"(r) : "f"(x)); return r;
}
__device__ __forceinline__ void packsplit(float x, float y,
                                          uint32_t& hp, uint32_t& lp)
{
    __nv_bfloat162 h = __floats2bfloat162_rn(x, y);
    __nv_bfloat162 l = __floats2bfloat162_rn(x - __bfloat162float(h.x),
                                             y - __bfloat162float(h.y));
    hp = *reinterpret_cast<uint32_t*>(&h);
    lp = *reinterpret_cast<uint32_t*>(&l);
}
__device__ __forceinline__ void split_store4(__nv_bfloat16* H, __nv_bfloat16* L,
                                             int off, float4 v)
{
    __nv_bfloat162 h0 = __floats2bfloat162_rn(v.x, v.y);
    __nv_bfloat162 h1 = __floats2bfloat162_rn(v.z, v.w);
    __nv_bfloat162 l0 = __floats2bfloat162_rn(v.x - __bfloat162float(h0.x),
                                              v.y - __bfloat162float(h0.y));
    __nv_bfloat162 l1 = __floats2bfloat162_rn(v.z - __bfloat162float(h1.x),
                                              v.w - __bfloat162float(h1.y));
    *reinterpret_cast<__nv_bfloat162*>(H + off)     = h0;
    *reinterpret_cast<__nv_bfloat162*>(H + off + 2) = h1;
    *reinterpret_cast<__nv_bfloat162*>(L + off)     = l0;
    *reinterpret_cast<__nv_bfloat162*>(L + off + 2) = l1;
}

// ---------------------------------------------------------------------------
// prep: fold LoRA into QKV weights.  W'[:, head] = W[:, head] @ M,
// M = I + 2 * A @ B (64x64, shared across heads).  K columns copied.
// Writes g_w2 (device global, referenced from device code only).
// ---------------------------------------------------------------------------
__global__ __launch_bounds__(256) void prep_w_kernel(
    const float* __restrict__ W,
    const float* __restrict__ aq, const float* __restrict__ bq,
    const float* __restrict__ av, const float* __restrict__ bv)
{
    __shared__ float Ws[64][65];
    __shared__ float Ms[64][65];

    const int tid = threadIdx.x;
    const int c0  = blockIdx.x * 64;
    const int r0  = blockIdx.y * 64;
    const int which = c0 >> 10;          // 0=q,1=k,2=v

    if (which == 1) {                    // copy K columns unchanged
        for (int ii = 0; ii < 4; ++ii) {
            const int idx = tid + ii * 256;
            const int i = idx >> 4, e4 = (idx & 15) * 4;
            float4 v = *reinterpret_cast<const float4*>(
                W + (size_t)(r0 + i) * 3072 + c0 + e4);
            *reinterpret_cast<float4*>(
                g_w2 + (size_t)(r0 + i) * 3072 + c0 + e4) = v;
        }
        return;
    }
    const float* A  = (which == 0) ? aq : av;   // [64,16]
    const float* Bm = (which == 0) ? bq : bv;   // [16,64]

    for (int ii = 0; ii < 4; ++ii) {
        const int idx = tid + ii * 256;
        const int i = idx >> 4, e4 = (idx & 15) * 4;
        float4 v = *reinterpret_cast<const float4*>(
            W + (size_t)(r0 + i) * 3072 + c0 + e4);
        Ws[i][e4 + 0] = v.x; Ws[i][e4 + 1] = v.y;
        Ws[i][e4 + 2] = v.z; Ws[i][e4 + 3] = v.w;
    }
    for (int ii = 0; ii < 16; ++ii) {
        const int idx = tid + ii * 256;              // 0..4095
        const int e = idx >> 6, d = idx & 63;
        float s = 0.f;
        for (int r = 0; r < 16; ++r)
            s += A[e * 16 + r] * Bm[r * 64 + d];
        Ms[e][d] = (e == d ? 1.f : 0.f) + 2.f * s;
    }
    __syncthreads();

    const int i  = tid & 63;
    const int dg = tid >> 6;                         // 0..3
    for (int jj = 0; jj < 16; ++jj) {
        const int col = dg * 16 + jj;
        float acc = 0.f;
        for (int e = 0; e < 64; ++e)
            acc += Ws[i][e] * Ms[e][col];
        g_w2[(size_t)(r0 + i) * 3072 + c0 + col] = acc;
    }
}

// grid 48 blocks x 64 threads; block handles 64 consecutive bias cols.
__global__ __launch_bounds__(64) void prep_b_kernel(
    const float* __restrict__ bqkv,
    const float* __restrict__ aq, const float* __restrict__ bq,
    const float* __restrict__ av, const float* __restrict__ bv)
{
    __shared__ float rs[16];
    const int base = blockIdx.x * 64;
    const int d    = threadIdx.x;
    const int which = (base + d) >> 10;
    if (which == 1) { g_b2[base + d] = bqkv[base + d]; return; }
    const float* A  = (which == 0) ? aq : av;
    const float* Bm = (which == 0) ? bq : bv;

    if (d < 16) {
        float s = 0.f;
        for (int e = 0; e < 64; ++e)
            s += bqkv[base + e] * A[e * 16 + d];
        rs[d] = s;
    }
    __syncthreads();
    float delta = 0.f;
    for (int j = 0; j < 16; ++j)
        delta += rs[j] * Bm[j * 64 + d];
    g_b2[base + d] = bqkv[base + d] + 2.f * delta;
}

// ---------------------------------------------------------------------------
// Generic split-bf16 GEMM: C[M,*] = A[M,1024] @ B[1024,Ncols] + bias
// Block 128x128, K-step 32, 8 warps.
// Bin == nullptr -> B = g_w2, bias = g_b2 (device globals, device-side only).
// Ain == nullptr -> A = g_o.
// mode 0: split-convert + store bf16 hi/lo into g_{q,k,v}{h,l}.
// mode 1: fp32 store to Cout.
// ---------------------------------------------------------------------------
__global__ __launch_bounds__(256) void gemm3_kernel(
    const float* __restrict__ Ain, const float* __restrict__ Bin,
    const float* __restrict__ biasin, float* __restrict__ Cout,
    int Ncols, int mode)
{
    __shared__ __nv_bfloat16 sAh[128 * 40], sAl[128 * 40];
    __shared__ __nv_bfloat16 sBh[32 * 136], sBl[32 * 136];

    const float* A    = Ain ? Ain : g_o;
    const float* B    = Bin ? Bin : g_w2;
    const float* bias = Bin ? biasin : g_b2;

    const int tid  = threadIdx.x;
    const int lane = tid & 31;
    const int warp = tid >> 5;
    const int m0   = (warp >> 2) * 64;
    const int n0   = (warp & 3) * 32;
    const int rB   = blockIdx.y * 128;
    const int cB   = blockIdx.x * 128;

    float acc[4][4][4];
    #pragma unroll
    for (int i = 0; i < 4; ++i)
        #pragma unroll
        for (int j = 0; j < 4; ++j)
            #pragma unroll
            for (int r = 0; r < 4; ++r) acc[i][j][r] = 0.f;

    const int arow = tid >> 3, acol = (tid & 7) * 4;
    const int brow = tid >> 5, bcol = (tid & 31) * 4;

    for (int k0 = 0; k0 < 1024; k0 += 32) {
        __syncthreads();
        #pragma unroll
        for (int i = 0; i < 4; ++i) {
            const int r = arow + i * 32;
            float4 v = *reinterpret_cast<const float4*>(
                A + (size_t)(rB + r) * 1024 + k0 + acol);
            split_store4(sAh, sAl, r * 40 + acol, v);
        }
        #pragma unroll
        for (int i = 0; i < 4; ++i) {
            const int r = brow + i * 8;
            float4 v = *reinterpret_cast<const float4*>(
                B + (size_t)(k0 + r) * Ncols + cB + bcol);
            split_store4(sBh, sBl, r * 136 + bcol, v);
        }
        __syncthreads();

        #pragma unroll
        for (int ks = 0; ks < 2; ++ks) {
            uint32_t ah[4][4], al[4][4];
            #pragma unroll
            for (int mi = 0; mi < 4; ++mi) {
                const int off = (m0 + mi * 16 + (lane & 15)) * 40
                              + ks * 16 + ((lane >> 4) << 3);
                ldsm4(ah[mi], sAh + off);
                ldsm4(al[mi], sAl + off);
            }
            uint32_t bh[4][2], bl[4][2];
            #pragma unroll
            for (int Jp = 0; Jp < 2; ++Jp) {
                const int off = (ks * 16 + (lane & 15)) * 136
                              + n0 + Jp * 16 + ((lane >> 4) << 3);
                uint32_t t[4];
                ldsm4t(t, sBh + off);
                bh[2*Jp][0] = t[0]; bh[2*Jp][1] = t[1];
                bh[2*Jp+1][0] = t[2]; bh[2*Jp+1][1] = t[3];
                ldsm4t(t, sBl + off);
                bl[2*Jp][0] = t[0]; bl[2*Jp][1] = t[1];
                bl[2*Jp+1][0] = t[2]; bl[2*Jp+1][1] = t[3];
            }
            #pragma unroll
            for (int mi = 0; mi < 4; ++mi)
                #pragma unroll
                for (int nj = 0; nj < 4; ++nj) {
                    mma_bf16(acc[mi][nj], ah[mi][0], ah[mi][1], ah[mi][2], ah[mi][3],
                             bh[nj][0], bh[nj][1]);
                    mma_bf16(acc[mi][nj], ah[mi][0], ah[mi][1], ah[mi][2], ah[mi][3],
                             bl[nj][0], bl[nj][1]);
                    mma_bf16(acc[mi][nj], al[mi][0], al[mi][1], al[mi][2], al[mi][3],
                             bh[nj][0], bh[nj][1]);
                }
        }
    }

    const int g  = lane >> 2;
    const int t2 = (lane & 3) * 2;
    #pragma unroll
    for (int mi = 0; mi < 4; ++mi)
        #pragma unroll
        for (int nj = 0; nj < 4; ++nj) {
            const int r = rB + m0 + mi * 16 + g;
            const int c = cB + n0 + nj * 8 + t2;
            const float b0 = bias[c], b1 = bias[c + 1];
            const float v00 = acc[mi][nj][0] + b0;
            const float v01 = acc[mi][nj][1] + b1;
            const float v10 = acc[mi][nj][2] + b0;
            const float v11 = acc[mi][nj][3] + b1;
            if (mode == 1) {
                Cout[(size_t)r * Ncols + c]           = v00;
                Cout[(size_t)r * Ncols + c + 1]       = v01;
                Cout[(size_t)(r + 8) * Ncols + c]     = v10;
                Cout[(size_t)(r + 8) * Ncols + c + 1] = v11;
            } else {
                const int which = c >> 10, rem = c & 1023;
                const int h = rem >> 6, d = rem & 63;
                __nv_bfloat16* dh = (which == 0) ? g_qh : (which == 1) ? g_kh : g_vh;
                __nv_bfloat16* dl = (which == 0) ? g_ql : (which == 1) ? g_kl : g_vl;
                const int b_  = r >> 11, n = r & 2047;
                const size_t ad0 = (((size_t)(b_ * HV + h)) * NV + n) * HDV + d;
                const size_t ad1 = ad0 + (size_t)8 * HDV;   // row r+8 (same b)
                uint32_t hp, lp;
                packsplit(v00, v01, hp, lp);
                *reinterpret_cast<uint32_t*>(dh + ad0) = hp;
                *reinterpret_cast<uint32_t*>(dl + ad0) = lp;
                packsplit(v10, v11, hp, lp);
                *reinterpret_cast<uint32_t*>(dh + ad1) = hp;
                *reinterpret_cast<uint32_t*>(dl + ad1) = lp;
            }
        }
}

// ---------------------------------------------------------------------------
// Flash attention on tensor cores (split-bf16 x3 for QK^T and PV).
// Block: 128 queries, 8 warps x 16 rows. 64-key tiles.
// ---------------------------------------------------------------------------
__global__ __launch_bounds__(256) void flash_mma_kernel()
{
    __shared__ __nv_bfloat16 sbuf[4 * 64 * 72];
    __nv_bfloat16* Kh = sbuf;
    __nv_bfloat16* Kl = sbuf + 4608;
    __nv_bfloat16* Vh = sbuf + 9216;
    __nv_bfloat16* Vl = sbuf + 13824;

    const int tid  = threadIdx.x;
    const int lane = tid & 31;
    const int w    = tid >> 5;
    const int bh   = blockIdx.y;
    const int b    = bh >> 4, h = bh & 15;
    const int q0   = blockIdx.x * 128;
    const size_t base = (size_t)bh * NV * 64;

    {
        const uint4* gh = reinterpret_cast<const uint4*>(g_qh + base + (size_t)q0 * 64);
        const uint4* gl = reinterpret_cast<const uint4*>(g_ql + base + (size_t)q0 * 64);
        #pragma unroll
        for (int i = 0; i < 4; ++i) {
            const int idx = tid + i * 256;
            const int row = idx >> 3, col8 = (idx & 7) * 8;
            *reinterpret_cast<uint4*>(&sbuf[row * 72 + col8])        = gh[idx];
            *reinterpret_cast<uint4*>(&sbuf[9216 + row * 72 + col8]) = gl[idx];
        }
    }
    __syncthreads();

    uint32_t qh[4][4], ql[4][4];
    #pragma unroll
    for (int kk = 0; kk < 4; ++kk) {
        const int off = (w * 16 + (lane & 15)) * 72
                      + kk * 16 + ((lane >> 4) << 3);
        ldsm4(qh[kk], sbuf + off);
        ldsm4(ql[kk], sbuf + 9216 + off);
    }

    float m0 = -1e30f, m1 = -1e30f, l0 = 0.f, l1 = 0.f;
    float acc[8][4];
    #pragma unroll
    for (int j = 0; j < 8; ++j)
        #pragma unroll
        for (int r = 0; r < 4; ++r) acc[j][r] = 0.f;

    const uint4* gkh = reinterpret_cast<const uint4*>(g_kh + base);
    const uint4* gkl = reinterpret_cast<const uint4*>(g_kl + base);
    const uint4* gvh = reinterpret_cast<const uint4*>(g_vh + base);
    const uint4* gvl = reinterpret_cast<const uint4*>(g_vl + base);

    for (int kt = 0; kt < NV / 64; ++kt) {
        __syncthreads();
        #pragma unroll
        for (int i = 0; i < 2; ++i) {
            const int idx = tid + i * 256;
            const int row = idx >> 3, col8 = (idx & 7) * 8;
            const int soff = row * 72 + col8;
            const int goff = kt * 512 + idx;
            *reinterpret_cast<uint4*>(&Kh[soff]) = gkh[goff];
            *reinterpret_cast<uint4*>(&Kl[soff]) = gkl[goff];
            *reinterpret_cast<uint4*>(&Vh[soff]) = gvh[goff];
            *reinterpret_cast<uint4*>(&Vl[soff]) = gvl[goff];
        }
        __syncthreads();

        float s[8][4];
        #pragma unroll
        for (int j = 0; j < 8; ++j)
            #pragma unroll
            for (int r = 0; r < 4; ++r) s[j][r] = 0.f;

        #pragma unroll
        for (int kk = 0; kk < 4; ++kk) {
            #pragma unroll
            for (int J = 0; J < 4; ++J) {
                const int keyrow = J * 16 + (lane & 7) + ((lane >> 4) << 3);
                const int dim    = kk * 16 + (((lane >> 3) & 1) << 3);
                const int off    = keyrow * 72 + dim;
                uint32_t kbh[4], kbl[4];
                ldsm4(kbh, Kh + off);
                ldsm4(kbl, Kl + off);
                mma_bf16(s[2*J],   qh[kk][0], qh[kk][1], qh[kk][2], qh[kk][3], kbh[0], kbh[1]);
                mma_bf16(s[2*J],   qh[kk][0], qh[kk][1], qh[kk][2], qh[kk][3], kbl[0], kbl[1]);
                mma_bf16(s[2*J],   ql[kk][0], ql[kk][1], ql[kk][2], ql[kk][3], kbh[0], kbh[1]);
                mma_bf16(s[2*J+1], qh[kk][0], qh[kk][1], qh[kk][2], qh[kk][3], kbh[2], kbh[3]);
                mma_bf16(s[2*J+1], qh[kk][0], qh[kk][1], qh[kk][2], qh[kk][3], kbl[2], kbl[3]);
                mma_bf16(s[2*J+1], ql[kk][0], ql[kk][1], ql[kk][2], ql[kk][3], kbh[2], kbh[3]);
            }
        }

        float mx0 = -1e30f, mx1 = -1e30f;
        #pragma unroll
        for (int j = 0; j < 8; ++j) {
            #pragma unroll
            for (int r = 0; r < 4; ++r) s[j][r] *= SM_SCALE;
            mx0 = fmaxf(mx0, fmaxf(s[j][0], s[j][1]));
            mx1 = fmaxf(mx1, fmaxf(s[j][2], s[j][3]));
        }
        mx0 = fmaxf(mx0, __shfl_xor_sync(0xffffffffu, mx0, 1));
        mx0 = fmaxf(mx0, __shfl_xor_sync(0xffffffffu, mx0, 2));
        mx1 = fmaxf(mx1, __shfl_xor_sync(0xffffffffu, mx1, 1));
        mx1 = fmaxf(mx1, __shfl_xor_sync(0xffffffffu, mx1, 2));
        const float mn0 = fmaxf(m0, mx0), mn1 = fmaxf(m1, mx1);
        const float al0 = ex2f(m0 - mn0), al1 = ex2f(m1 - mn1);
        l0 *= al0; l1 *= al1;
        #pragma unroll
        for (int j = 0; j < 8; ++j) {
            acc[j][0] *= al0; acc[j][1] *= al0;
            acc[j][2] *= al1; acc[j][3] *= al1;
            s[j][0] = ex2f(s[j][0] - mn0);
            s[j][1] = ex2f(s[j][1] - mn0);
            s[j][2] = ex2f(s[j][2] - mn1);
            s[j][3] = ex2f(s[j][3] - mn1);
            l0 += s[j][0] + s[j][1];
            l1 += s[j][2] + s[j][3];
        }
        m0 = mn0; m1 = mn1;

        #pragma unroll
        for (int kk = 0; kk < 4; ++kk) {
            uint32_t pah[4], pal[4];
            packsplit(s[2*kk][0],   s[2*kk][1],   pah[0], pal[0]);
            packsplit(s[2*kk][2],   s[2*kk][3],   pah[1], pal[1]);
            packsplit(s[2*kk+1][0], s[2*kk+1][1], pah[2], pal[2]);
            packsplit(s[2*kk+1][2], s[2*kk+1][3], pah[3], pal[3]);
            #pragma unroll
            for (int J = 0; J < 4; ++J) {
                const int key = kk * 16 + (lane & 15);
                const int dim = J * 16 + ((lane >> 4) << 3);
                const int off = key * 72 + dim;
                uint32_t vbh[4], vbl[4];
                ldsm4t(vbh, Vh + off);
                ldsm4t(vbl, Vl + off);
                mma_bf16(acc[2*J],   pah[0], pah[1], pah[2], pah[3], vbh[0], vbh[1]);
                mma_bf16(acc[2*J],   pah[0], pah[1], pah[2], pah[3], vbl[0], vbl[1]);
                mma_bf16(acc[2*J],   pal[0], pal[1], pal[2], pal[3], vbh[0], vbh[1]);
                mma_bf16(acc[2*J+1], pah[0], pah[1], pah[2], pah[3], vbh[2], vbh[3]);
                mma_bf16(acc[2*J+1], pah[0], pah[1], pah[2], pah[3], vbl[2], vbl[3]);
                mma_bf16(acc[2*J+1], pal[0], pal[1], pal[2], pal[3], vbh[2], vbh[3]);
            }
        }
    }

    l0 += __shfl_xor_sync(0xffffffffu, l0, 1);
    l0 += __shfl_xor_sync(0xffffffffu, l0, 2);
    l1 += __shfl_xor_sync(0xffffffffu, l1, 1);
    l1 += __shfl_xor_sync(0xffffffffu, l1, 2);
    const float inv0 = 1.f / l0, inv1 = 1.f / l1;

    const int g  = lane >> 2;
    const int t2 = (lane & 3) * 2;
    const int row0 = q0 + w * 16 + g;
    const size_t ob = ((size_t)b * NV + row0) * CV + h * 64;
    #pragma unroll
    for (int j = 0; j < 8; ++j) {
        const int c = j * 8 + t2;
        *reinterpret_cast<float2*>(&g_o[ob + c]) =
            make_float2(acc[j][0] * inv0, acc[j][1] * inv0);
        *reinterpret_cast<float2*>(&g_o[ob + (size_t)8 * CV + c]) =
            make_float2(acc[j][2] * inv1, acc[j][3] * inv1);
    }
}

// ---------------------------------------------------------------------------
extern "C" void kernel_launch(void* const* d_in, const int* in_sizes, int n_in,
                              void* d_out, int out_size)
{
    const float* x      = (const float*)d_in[0];
    const float* w_qkv  = (const float*)d_in[1];
    const float* b_qkv  = (const float*)d_in[2];
    const float* a_q    = (const float*)d_in[3];
    const float* b_q    = (const float*)d_in[4];
    const float* a_v    = (const float*)d_in[5];
    const float* b_v    = (const float*)d_in[6];
    const float* w_proj = (const float*)d_in[7];
    const float* b_proj = (const float*)d_in[8];
    float* out = (float*)d_out;

    (void)in_sizes; (void)n_in; (void)out_size;

    // 0) fold LoRA into QKV weights/bias (into g_w2/g_b2 device globals)
    prep_w_kernel<<<dim3(48, 16), 256>>>(w_qkv, a_q, b_q, a_v, b_v);
    prep_b_kernel<<<48, 64>>>(b_qkv, a_q, b_q, a_v, b_v);

    // 1) QKV GEMM (split-bf16 TC), B/bias = g_w2/g_b2 via nullptr sentinel
    gemm3_kernel<<<dim3(3 * CV / 128, MROWS / 128), 256>>>(
        x, nullptr, nullptr, out, 3 * CV, 0);

    // 2) attention (TC) -> g_o fp32
    flash_mma_kernel<<<dim3(NV / 128, BV * HV), 256>>>();

    // 3) projection (split-bf16 TC) -> out
    gemm3_kernel<<<dim3(CV / 128, MROWS / 128), 256>>>(
        nullptr, w_proj, b_proj, out, CV, 1);
}